// round 11
// baseline (speedup 1.0000x reference)
#include <cuda_runtime.h>
#include <cuda_bf16.h>
#include <math.h>
#include <stdint.h>

#define N_MAX 50000
#define E_MAX 800000
#define F 128
#define N_GRAPHS 64
#define N_CLS 10
#define PAD 132   // floats per SMEM row (128 + 4 to break bank conflicts)
#define NCHUNK 4

// ---------------- device scratch ----------------
__device__ float g_xwA[(size_t)N_MAX * F];     // ping-pong h@W buffers
__device__ float g_xwB[(size_t)N_MAX * F];
__device__ float g_h[(size_t)N_MAX * F];       // layer output (relu'd)
__device__ float g_deg[N_MAX];
__device__ float g_dinv[N_MAX];
__device__ float g_dinv2[N_MAX];
__device__ float g_sumsq;
__device__ float g_pool[N_GRAPHS * F];
__device__ int   g_idx64;
// CSR by target node (built once, reused 3 layers)
__device__ int   g_cnt[N_MAX];
__device__ int   g_start[N_MAX];
__device__ int   g_cursor[N_MAX];
__device__ int   g_csr_row[E_MAX];
__device__ float g_csr_w[E_MAX];

// ---------------- index helpers ----------------
__device__ __forceinline__ int load_idx(const void* p, long long i, int is64) {
    if (is64) return (int)((const long long*)p)[i];
    return ((const int*)p)[i];
}

// ---------------- init: dtype detect (block 0) + resets ----------------
__global__ void k_init(const int* __restrict__ ei32, int E, int n) {
    int i = blockIdx.x * blockDim.x + threadIdx.x;
    if (i < n) { g_deg[i] = 0.0f; g_cnt[i] = 0; g_cursor[i] = 0; }
    if (i < N_GRAPHS * F) ((int*)g_pool)[i] = 0;
    if (i == 0) g_sumsq = 0.0f;
    if (blockIdx.x == 0) {
        __shared__ int anynz;
        if (threadIdx.x == 0) anynz = 0;
        __syncthreads();
        int samples = min(E, 2048);
        for (int t = threadIdx.x; t < samples; t += blockDim.x)
            if (ei32[2 * t + 1] != 0) anynz = 1;
        __syncthreads();
        if (threadIdx.x == 0) g_idx64 = anynz ? 0 : 1;
    }
}

// one edge pass: sumsq reduction + raw deg accumulation + cnt
__global__ void k_edge1(const void* __restrict__ ei, const float* __restrict__ ew, int E) {
    int e = blockIdx.x * blockDim.x + threadIdx.x;
    int is64 = g_idx64;
    float v = 0.0f;
    if (e < E) {
        v = ew[e];
        int c = load_idx(ei, (long long)E + e, is64);
        atomicAdd(&g_deg[c], v);
        atomicAdd(&g_cnt[c], 1);
    }
    float s = v * v;
    #pragma unroll
    for (int o = 16; o > 0; o >>= 1) s += __shfl_down_sync(0xffffffffu, s, o);
    __shared__ float ws[8];
    int lane = threadIdx.x & 31, wid = threadIdx.x >> 5;
    if (lane == 0) ws[wid] = s;
    __syncthreads();
    if (wid == 0) {
        s = (lane < (blockDim.x >> 5)) ? ws[lane] : 0.0f;
        #pragma unroll
        for (int o = 4; o > 0; o >>= 1) s += __shfl_down_sync(0xffffffffu, s, o);
        if (lane == 0) atomicAdd(&g_sumsq, s);
    }
}

__device__ __forceinline__ float inv_l2norm() {
    return 1.0f / fmaxf(sqrtf(g_sumsq), 1e-12f);
}

__global__ void k_dinv(int n) {
    int i = blockIdx.x * blockDim.x + threadIdx.x;
    if (i >= n) return;
    float d = 1.0f + inv_l2norm() * g_deg[i];
    float di = (d > 0.0f) ? rsqrtf(d) : 0.0f;
    g_dinv[i] = di;
    g_dinv2[i] = di * di;
}

__global__ void k_scan(int n) {
    __shared__ int tsum[1024];
    int t = threadIdx.x;
    int chunk = (n + 1023) / 1024;
    int lo = t * chunk, hi = min(lo + chunk, n);
    int s = 0;
    for (int i = lo; i < hi; i++) s += g_cnt[i];
    tsum[t] = s;
    __syncthreads();
    for (int o = 1; o < 1024; o <<= 1) {
        int v = (t >= o) ? tsum[t - o] : 0;
        __syncthreads();
        tsum[t] += v;
        __syncthreads();
    }
    int run = (t > 0) ? tsum[t - 1] : 0;
    for (int i = lo; i < hi; i++) {
        g_start[i] = run;
        run += g_cnt[i];
    }
}

__global__ void k_fill(const void* __restrict__ ei, const float* __restrict__ ew, int E) {
    int e = blockIdx.x * blockDim.x + threadIdx.x;
    if (e >= E) return;
    int is64 = g_idx64;
    float invn = inv_l2norm();
    int r = load_idx(ei, e, is64);
    int c = load_idx(ei, (long long)E + e, is64);
    float w = g_dinv[r] * (ew[e] * invn) * g_dinv[c];
    int p = atomicAdd(&g_cursor[c], 1);
    int slot = g_start[c] + p;
    g_csr_row[slot] = r;
    g_csr_w[slot] = w;
}

// ---------------- tf32 mma.sync GEMM: xw = A @ W (row_base chunk offset) ----------------
__device__ __forceinline__ uint32_t f2tf32(float f) {
    uint32_t r;
    asm("cvt.rna.tf32.f32 %0, %1;" : "=r"(r) : "f"(f));
    return r;
}

__global__ void __launch_bounds__(256, 1) k_gemm_mma(const float* __restrict__ A,
                                                     const float* __restrict__ W,
                                                     float* __restrict__ xw, int n,
                                                     int row_base) {
    extern __shared__ uint32_t sm[];
    uint32_t* As = sm;               // 128 x PAD
    uint32_t* Ws = sm + 128 * PAD;   // 128 x PAD
    int tid = threadIdx.x;
    int row0 = row_base + blockIdx.x * 128;

    const float4* w4 = (const float4*)W;
    #pragma unroll
    for (int j = 0; j < 16; j++) {
        int idx4 = tid + j * 256;
        int el = idx4 * 4;
        int r = el >> 7, c = el & 127;
        float4 v = w4[idx4];
        uint32_t* dst = &Ws[r * PAD + c];
        dst[0] = f2tf32(v.x); dst[1] = f2tf32(v.y);
        dst[2] = f2tf32(v.z); dst[3] = f2tf32(v.w);
    }
    const float4* a4 = (const float4*)A;
    #pragma unroll
    for (int j = 0; j < 16; j++) {
        int idx4 = tid + j * 256;
        int el = idx4 * 4;
        int r = el >> 7, c = el & 127;
        int gr = row0 + r;
        float4 v = (gr < n) ? a4[(size_t)gr * 32 + (c >> 2)] : make_float4(0.f, 0.f, 0.f, 0.f);
        uint32_t* dst = &As[r * PAD + c];
        dst[0] = f2tf32(v.x); dst[1] = f2tf32(v.y);
        dst[2] = f2tf32(v.z); dst[3] = f2tf32(v.w);
    }
    __syncthreads();

    int lane = tid & 31, warp = tid >> 5;
    int wm = warp >> 1, wn = warp & 1;
    int m0 = wm * 32, n0 = wn * 64;
    int grp = lane >> 2, thr = lane & 3;

    float acc[2][8][4];
    #pragma unroll
    for (int f = 0; f < 2; f++)
        #pragma unroll
        for (int g = 0; g < 8; g++)
            #pragma unroll
            for (int q = 0; q < 4; q++) acc[f][g][q] = 0.0f;

    #pragma unroll 4
    for (int s = 0; s < 16; s++) {
        int k0 = s * 8;
        uint32_t a[2][4];
        #pragma unroll
        for (int f = 0; f < 2; f++) {
            int rl = m0 + f * 16 + grp;
            a[f][0] = As[rl * PAD + k0 + thr];
            a[f][1] = As[(rl + 8) * PAD + k0 + thr];
            a[f][2] = As[rl * PAD + k0 + 4 + thr];
            a[f][3] = As[(rl + 8) * PAD + k0 + 4 + thr];
        }
        #pragma unroll
        for (int g = 0; g < 8; g++) {
            uint32_t b0 = Ws[(k0 + thr) * PAD + n0 + g * 8 + grp];
            uint32_t b1 = Ws[(k0 + 4 + thr) * PAD + n0 + g * 8 + grp];
            #pragma unroll
            for (int f = 0; f < 2; f++) {
                asm volatile(
                    "mma.sync.aligned.m16n8k8.row.col.f32.tf32.tf32.f32 "
                    "{%0,%1,%2,%3}, {%4,%5,%6,%7}, {%8,%9}, {%0,%1,%2,%3};"
                    : "+f"(acc[f][g][0]), "+f"(acc[f][g][1]),
                      "+f"(acc[f][g][2]), "+f"(acc[f][g][3])
                    : "r"(a[f][0]), "r"(a[f][1]), "r"(a[f][2]), "r"(a[f][3]),
                      "r"(b0), "r"(b1));
            }
        }
    }

    #pragma unroll
    for (int f = 0; f < 2; f++) {
        int rl = row0 + m0 + f * 16 + grp;
        int rh = rl + 8;
        #pragma unroll
        for (int g = 0; g < 8; g++) {
            int col = n0 + g * 8 + thr * 2;
            if (rl < n)
                *(float2*)&xw[(size_t)rl * F + col] = make_float2(acc[f][g][0], acc[f][g][1]);
            if (rh < n)
                *(float2*)&xw[(size_t)rh * F + col] = make_float2(acc[f][g][2], acc[f][g][3]);
        }
    }
}

// ---------------- CSR gather (proven body; row-chunked) ----------------
__global__ void k_gather(const float* __restrict__ xw, const float* __restrict__ b,
                         float* __restrict__ out, int row_base, int row_end) {
    int warp = row_base + ((blockIdx.x * blockDim.x + threadIdx.x) >> 5);
    int lane = threadIdx.x & 31;
    if (warp >= row_end) return;

    const float4* xwv = (const float4*)xw;
    float4 bb = *(const float4*)&b[lane * 4];
    float d2 = g_dinv2[warp];
    float4 xv = __ldg(&xwv[(size_t)warp * 32 + lane]);
    float4 acc = make_float4(fmaf(d2, xv.x, bb.x), fmaf(d2, xv.y, bb.y),
                             fmaf(d2, xv.z, bb.z), fmaf(d2, xv.w, bb.w));

    int s = g_start[warp];
    int cnt = g_cnt[warp];
    for (int base = 0; base < cnt; base += 32) {
        int m = min(32, cnt - base);
        int r = 0; float w = 0.0f;
        if (lane < m) {
            r = g_csr_row[s + base + lane];
            w = g_csr_w[s + base + lane];
        }
        #pragma unroll 4
        for (int j = 0; j < m; j++) {
            int rj = __shfl_sync(0xffffffffu, r, j);
            float wj = __shfl_sync(0xffffffffu, w, j);
            float4 v = __ldg(&xwv[(size_t)rj * 32 + lane]);
            acc.x = fmaf(wj, v.x, acc.x);
            acc.y = fmaf(wj, v.y, acc.y);
            acc.z = fmaf(wj, v.z, acc.z);
            acc.w = fmaf(wj, v.w, acc.w);
        }
    }
    float4 o = make_float4(fmaxf(acc.x, 0.0f), fmaxf(acc.y, 0.0f),
                           fmaxf(acc.z, 0.0f), fmaxf(acc.w, 0.0f));
    *(float4*)&out[(size_t)warp * F + lane * 4] = o;
}

// ---------------- segment-max pool (row-chunked) ----------------
__global__ void k_pool(const float* __restrict__ h, const void* __restrict__ batch,
                       int row_base, int row_end) {
    int col = threadIdx.x;
    int start = row_base + blockIdx.x * 128;
    if (start >= row_end) return;
    int is64 = g_idx64;
    int end = min(start + 128, row_end);
    int cur = load_idx(batch, start, is64);
    float m = 0.0f;
    for (int i = start; i < end; i++) {
        int g = load_idx(batch, i, is64);
        float v = h[(size_t)i * F + col];
        if (g != cur) {
            atomicMax((int*)&g_pool[cur * F + col], __float_as_int(m));
            cur = g;
            m = v;
        } else {
            m = fmaxf(m, v);
        }
    }
    atomicMax((int*)&g_pool[cur * F + col], __float_as_int(m));
}

// ---------------- head ----------------
__global__ void k_head(const float* __restrict__ Wl, const float* __restrict__ bl,
                       float* __restrict__ out) {
    int t = blockIdx.x * blockDim.x + threadIdx.x;
    if (t >= N_GRAPHS * N_CLS) return;
    int g = t / N_CLS, cls = t % N_CLS;
    float s = bl[cls];
    #pragma unroll 8
    for (int c = 0; c < F; c++)
        s = fmaf(g_pool[g * F + c], Wl[c * N_CLS + cls], s);
    out[t] = s;
}

// ---------------- launch: fork/join + chunk pipeline (joins AFTER each boundary loop) ----------------
extern "C" void kernel_launch(void* const* d_in, const int* in_sizes, int n_in,
                              void* d_out, int out_size) {
    const float* x     = (const float*)d_in[0];
    const void*  ei    = d_in[1];
    const float* ew    = (const float*)d_in[2];
    const void*  batch = d_in[3];
    const float* W1 = (const float*)d_in[4];
    const float* b1 = (const float*)d_in[5];
    const float* W2 = (const float*)d_in[6];
    const float* b2 = (const float*)d_in[7];
    const float* W3 = (const float*)d_in[8];
    const float* b3 = (const float*)d_in[9];
    const float* Wl = (const float*)d_in[10];
    const float* bl = (const float*)d_in[11];
    float* out = (float*)d_out;

    int n = in_sizes[0] / F;
    int E = in_sizes[2];

    float *p_xwA, *p_xwB, *p_h;
    cudaGetSymbolAddress((void**)&p_xwA, g_xwA);
    cudaGetSymbolAddress((void**)&p_xwB, g_xwB);
    cudaGetSymbolAddress((void**)&p_h,   g_h);

    const int smem_bytes = 2 * 128 * PAD * (int)sizeof(float);  // 135168 B
    cudaFuncSetAttribute(k_gemm_mma, cudaFuncAttributeMaxDynamicSharedMemorySize, smem_bytes);

    cudaStream_t s1, s2;
    cudaStreamCreateWithFlags(&s1, cudaStreamNonBlocking);
    cudaStreamCreateWithFlags(&s2, cudaStreamNonBlocking);
    const int NEV = 64;
    cudaEvent_t ev[NEV];
    for (int i = 0; i < NEV; i++) cudaEventCreateWithFlags(&ev[i], cudaEventDisableTiming);
    int evi = 0;

    int tb = 256;
    int eg = (E + tb - 1) / tb;
    int ng = (n + tb - 1) / tb;
    int gemm_grid_full = (n + 127) / 128;

    // chunk bounds (128-aligned)
    int rows_per_chunk = ((n + NCHUNK - 1) / NCHUNK + 127) & ~127;
    int c0[NCHUNK], c1[NCHUNK];
    for (int c = 0; c < NCHUNK; c++) {
        c0[c] = c * rows_per_chunk;
        if (c0[c] > n) c0[c] = n;
        c1[c] = min(c0[c] + rows_per_chunk, n);
    }

    // fork full GEMM1 -> xwA onto s1
    cudaEvent_t eFork = ev[evi++];
    cudaEventRecord(eFork, 0);
    cudaStreamWaitEvent(s1, eFork, 0);
    k_gemm_mma<<<gemm_grid_full, 256, smem_bytes, s1>>>(x, W1, p_xwA, n, 0);
    cudaEvent_t eG1 = ev[evi++];
    cudaEventRecord(eG1, s1);

    // CSR + normalization chain on default stream
    k_init<<<ng, tb>>>((const int*)ei, E, n);
    k_edge1<<<eg, tb>>>(ei, ew, E);
    cudaEvent_t eFork2 = ev[evi++];
    cudaEventRecord(eFork2, 0);
    cudaStreamWaitEvent(s2, eFork2, 0);
    k_dinv<<<ng, tb, 0, s2>>>(n);
    cudaEvent_t eDinv = ev[evi++];
    cudaEventRecord(eDinv, s2);
    k_scan<<<1, 1024>>>(n);
    cudaStreamWaitEvent(0, eDinv, 0);
    k_fill<<<eg, tb>>>(ei, ew, E);
    cudaStreamWaitEvent(0, eG1, 0);   // join GEMM1

    // ---- boundary 1: gather1 chunks (xwA -> h) ∥ GEMM2 chunks (h -> xwB) ----
    {
        cudaEvent_t done[NCHUNK] = {};
        for (int c = 0; c < NCHUNK; c++) {
            if (c0[c] >= c1[c]) continue;
            int rows = c1[c] - c0[c];
            k_gather<<<(rows * 32 + tb - 1) / tb, tb>>>(p_xwA, b1, p_h, c0[c], c1[c]);
            cudaEvent_t eGa = ev[evi++];
            cudaEventRecord(eGa, 0);
            cudaStreamWaitEvent(s1, eGa, 0);
            k_gemm_mma<<<(rows + 127) / 128, 256, smem_bytes, s1>>>(p_h, W2, p_xwB, n, c0[c]);
            done[c] = ev[evi++];
            cudaEventRecord(done[c], s1);
        }
        for (int c = 0; c < NCHUNK; c++)
            if (done[c]) cudaStreamWaitEvent(0, done[c], 0);   // join AFTER loop
    }
    // ---- boundary 2: gather2 chunks (xwB -> h) ∥ GEMM3 chunks (h -> xwA) ----
    {
        cudaEvent_t done[NCHUNK] = {};
        for (int c = 0; c < NCHUNK; c++) {
            if (c0[c] >= c1[c]) continue;
            int rows = c1[c] - c0[c];
            k_gather<<<(rows * 32 + tb - 1) / tb, tb>>>(p_xwB, b2, p_h, c0[c], c1[c]);
            cudaEvent_t eGa = ev[evi++];
            cudaEventRecord(eGa, 0);
            cudaStreamWaitEvent(s1, eGa, 0);
            k_gemm_mma<<<(rows + 127) / 128, 256, smem_bytes, s1>>>(p_h, W3, p_xwA, n, c0[c]);
            done[c] = ev[evi++];
            cudaEventRecord(done[c], s1);
        }
        for (int c = 0; c < NCHUNK; c++)
            if (done[c]) cudaStreamWaitEvent(0, done[c], 0);
    }
    // ---- boundary 3: gather3 chunks (xwA -> h) ∥ pool chunks ----
    {
        cudaEvent_t done[NCHUNK] = {};
        for (int c = 0; c < NCHUNK; c++) {
            if (c0[c] >= c1[c]) continue;
            int rows = c1[c] - c0[c];
            k_gather<<<(rows * 32 + tb - 1) / tb, tb>>>(p_xwA, b3, p_h, c0[c], c1[c]);
            cudaEvent_t eGa = ev[evi++];
            cudaEventRecord(eGa, 0);
            cudaStreamWaitEvent(s1, eGa, 0);
            k_pool<<<(rows + 127) / 128, 128, 0, s1>>>(p_h, batch, c0[c], c1[c]);
            done[c] = ev[evi++];
            cudaEventRecord(done[c], s1);
        }
        for (int c = 0; c < NCHUNK; c++)
            if (done[c]) cudaStreamWaitEvent(0, done[c], 0);
    }

    k_head<<<(N_GRAPHS * N_CLS + 127) / 128, 128>>>(Wl, bl, out);

    for (int i = 0; i < NEV; i++) cudaEventDestroy(ev[i]);
    cudaStreamDestroy(s1);
    cudaStreamDestroy(s2);
}

// round 12
// speedup vs baseline: 2.0437x; 2.0437x over previous
#include <cuda_runtime.h>
#include <cuda_bf16.h>
#include <math.h>
#include <stdint.h>

#define N_MAX 50000
#define E_MAX 800000
#define F 128
#define N_GRAPHS 64
#define N_CLS 10
#define PAD 132   // floats per SMEM row (128 + 4 to break bank conflicts)

// ---------------- device scratch ----------------
__device__ float g_xw[(size_t)N_MAX * F];      // h @ W
__device__ float g_h[(size_t)N_MAX * F];       // layer output (relu'd)
__device__ float g_deg[N_MAX];                 // raw sum of ew at target
__device__ float g_dinv[N_MAX];
__device__ float g_dinv2[N_MAX];
__device__ float g_sumsq;
__device__ float g_pool[N_GRAPHS * F];
__device__ int   g_idx64;
// CSR by target node (built once, reused 3 layers)
__device__ int   g_cnt[N_MAX];
__device__ int   g_start[N_MAX];
__device__ int   g_cursor[N_MAX];
__device__ int   g_csr_row[E_MAX];
__device__ float g_csr_w[E_MAX];

// ---------------- index helpers ----------------
__device__ __forceinline__ int load_idx(const void* p, long long i, int is64) {
    if (is64) return (int)((const long long*)p)[i];
    return ((const int*)p)[i];
}

// ---------------- init: dtype detect (block 0) + resets ----------------
__global__ void k_init(const int* __restrict__ ei32, int E, int n) {
    int i = blockIdx.x * blockDim.x + threadIdx.x;
    if (i < n) { g_deg[i] = 0.0f; g_cnt[i] = 0; g_cursor[i] = 0; }
    if (i < N_GRAPHS * F) ((int*)g_pool)[i] = 0;
    if (i == 0) g_sumsq = 0.0f;
    if (blockIdx.x == 0) {
        __shared__ int anynz;
        if (threadIdx.x == 0) anynz = 0;
        __syncthreads();
        int samples = min(E, 2048);
        for (int t = threadIdx.x; t < samples; t += blockDim.x)
            if (ei32[2 * t + 1] != 0) anynz = 1;
        __syncthreads();
        if (threadIdx.x == 0) g_idx64 = anynz ? 0 : 1;
    }
}

// one edge pass: sumsq reduction + raw deg accumulation + cnt
__global__ void k_edge1(const void* __restrict__ ei, const float* __restrict__ ew, int E) {
    int e = blockIdx.x * blockDim.x + threadIdx.x;
    int is64 = g_idx64;
    float v = 0.0f;
    if (e < E) {
        v = ew[e];
        int c = load_idx(ei, (long long)E + e, is64);
        atomicAdd(&g_deg[c], v);
        atomicAdd(&g_cnt[c], 1);
    }
    float s = v * v;
    #pragma unroll
    for (int o = 16; o > 0; o >>= 1) s += __shfl_down_sync(0xffffffffu, s, o);
    __shared__ float ws[8];
    int lane = threadIdx.x & 31, wid = threadIdx.x >> 5;
    if (lane == 0) ws[wid] = s;
    __syncthreads();
    if (wid == 0) {
        s = (lane < (blockDim.x >> 5)) ? ws[lane] : 0.0f;
        #pragma unroll
        for (int o = 4; o > 0; o >>= 1) s += __shfl_down_sync(0xffffffffu, s, o);
        if (lane == 0) atomicAdd(&g_sumsq, s);
    }
}

__device__ __forceinline__ float inv_l2norm() {
    return 1.0f / fmaxf(sqrtf(g_sumsq), 1e-12f);
}

__global__ void k_dinv(int n) {
    int i = blockIdx.x * blockDim.x + threadIdx.x;
    if (i >= n) return;
    float d = 1.0f + inv_l2norm() * g_deg[i];
    float di = (d > 0.0f) ? rsqrtf(d) : 0.0f;
    g_dinv[i] = di;
    g_dinv2[i] = di * di;
}

__global__ void k_scan(int n) {
    __shared__ int tsum[1024];
    int t = threadIdx.x;
    int chunk = (n + 1023) / 1024;
    int lo = t * chunk, hi = min(lo + chunk, n);
    int s = 0;
    for (int i = lo; i < hi; i++) s += g_cnt[i];
    tsum[t] = s;
    __syncthreads();
    for (int o = 1; o < 1024; o <<= 1) {
        int v = (t >= o) ? tsum[t - o] : 0;
        __syncthreads();
        tsum[t] += v;
        __syncthreads();
    }
    int run = (t > 0) ? tsum[t - 1] : 0;
    for (int i = lo; i < hi; i++) {
        g_start[i] = run;
        run += g_cnt[i];
    }
}

__global__ void k_fill(const void* __restrict__ ei, const float* __restrict__ ew, int E) {
    int e = blockIdx.x * blockDim.x + threadIdx.x;
    if (e >= E) return;
    int is64 = g_idx64;
    float invn = inv_l2norm();
    int r = load_idx(ei, e, is64);
    int c = load_idx(ei, (long long)E + e, is64);
    float w = g_dinv[r] * (ew[e] * invn) * g_dinv[c];
    int p = atomicAdd(&g_cursor[c], 1);
    int slot = g_start[c] + p;
    g_csr_row[slot] = r;
    g_csr_w[slot] = w;
}

// ---------------- tf32 mma.sync GEMM: xw = A @ W ----------------
__device__ __forceinline__ uint32_t f2tf32(float f) {
    uint32_t r;
    asm("cvt.rna.tf32.f32 %0, %1;" : "=r"(r) : "f"(f));
    return r;
}

__global__ void __launch_bounds__(256, 1) k_gemm_mma(const float* __restrict__ A,
                                                     const float* __restrict__ W,
                                                     float* __restrict__ xw, int n) {
    extern __shared__ uint32_t sm[];
    uint32_t* As = sm;               // 128 x PAD
    uint32_t* Ws = sm + 128 * PAD;   // 128 x PAD
    int tid = threadIdx.x;
    int row0 = blockIdx.x * 128;

    const float4* w4 = (const float4*)W;
    #pragma unroll
    for (int j = 0; j < 16; j++) {
        int idx4 = tid + j * 256;
        int el = idx4 * 4;
        int r = el >> 7, c = el & 127;
        float4 v = w4[idx4];
        uint32_t* dst = &Ws[r * PAD + c];
        dst[0] = f2tf32(v.x); dst[1] = f2tf32(v.y);
        dst[2] = f2tf32(v.z); dst[3] = f2tf32(v.w);
    }
    const float4* a4 = (const float4*)A;
    #pragma unroll
    for (int j = 0; j < 16; j++) {
        int idx4 = tid + j * 256;
        int el = idx4 * 4;
        int r = el >> 7, c = el & 127;
        int gr = row0 + r;
        float4 v = (gr < n) ? a4[(size_t)gr * 32 + (c >> 2)] : make_float4(0.f, 0.f, 0.f, 0.f);
        uint32_t* dst = &As[r * PAD + c];
        dst[0] = f2tf32(v.x); dst[1] = f2tf32(v.y);
        dst[2] = f2tf32(v.z); dst[3] = f2tf32(v.w);
    }
    __syncthreads();

    int lane = tid & 31, warp = tid >> 5;
    int wm = warp >> 1, wn = warp & 1;
    int m0 = wm * 32, n0 = wn * 64;
    int grp = lane >> 2, thr = lane & 3;

    float acc[2][8][4];
    #pragma unroll
    for (int f = 0; f < 2; f++)
        #pragma unroll
        for (int g = 0; g < 8; g++)
            #pragma unroll
            for (int q = 0; q < 4; q++) acc[f][g][q] = 0.0f;

    #pragma unroll 4
    for (int s = 0; s < 16; s++) {
        int k0 = s * 8;
        uint32_t a[2][4];
        #pragma unroll
        for (int f = 0; f < 2; f++) {
            int rl = m0 + f * 16 + grp;
            a[f][0] = As[rl * PAD + k0 + thr];
            a[f][1] = As[(rl + 8) * PAD + k0 + thr];
            a[f][2] = As[rl * PAD + k0 + 4 + thr];
            a[f][3] = As[(rl + 8) * PAD + k0 + 4 + thr];
        }
        #pragma unroll
        for (int g = 0; g < 8; g++) {
            uint32_t b0 = Ws[(k0 + thr) * PAD + n0 + g * 8 + grp];
            uint32_t b1 = Ws[(k0 + 4 + thr) * PAD + n0 + g * 8 + grp];
            #pragma unroll
            for (int f = 0; f < 2; f++) {
                asm volatile(
                    "mma.sync.aligned.m16n8k8.row.col.f32.tf32.tf32.f32 "
                    "{%0,%1,%2,%3}, {%4,%5,%6,%7}, {%8,%9}, {%0,%1,%2,%3};"
                    : "+f"(acc[f][g][0]), "+f"(acc[f][g][1]),
                      "+f"(acc[f][g][2]), "+f"(acc[f][g][3])
                    : "r"(a[f][0]), "r"(a[f][1]), "r"(a[f][2]), "r"(a[f][3]),
                      "r"(b0), "r"(b1));
            }
        }
    }

    #pragma unroll
    for (int f = 0; f < 2; f++) {
        int rl = row0 + m0 + f * 16 + grp;
        int rh = rl + 8;
        #pragma unroll
        for (int g = 0; g < 8; g++) {
            int col = n0 + g * 8 + thr * 2;
            if (rl < n)
                *(float2*)&xw[(size_t)rl * F + col] = make_float2(acc[f][g][0], acc[f][g][1]);
            if (rh < n)
                *(float2*)&xw[(size_t)rh * F + col] = make_float2(acc[f][g][2], acc[f][g][3]);
        }
    }
}

// ---------------- CSR gather: out = relu(b + dinv2*xw[i] + sum w*xw[r]) ----------------
__global__ void k_gather(const float* __restrict__ xw, const float* __restrict__ b,
                         float* __restrict__ out, int n) {
    int warp = (blockIdx.x * blockDim.x + threadIdx.x) >> 5;
    int lane = threadIdx.x & 31;
    if (warp >= n) return;

    const float4* xwv = (const float4*)xw;
    float4 bb = *(const float4*)&b[lane * 4];
    float d2 = g_dinv2[warp];
    float4 xv = __ldg(&xwv[(size_t)warp * 32 + lane]);
    float4 acc = make_float4(fmaf(d2, xv.x, bb.x), fmaf(d2, xv.y, bb.y),
                             fmaf(d2, xv.z, bb.z), fmaf(d2, xv.w, bb.w));

    int s = g_start[warp];
    int cnt = g_cnt[warp];
    for (int base = 0; base < cnt; base += 32) {
        int m = min(32, cnt - base);
        int r = 0; float w = 0.0f;
        if (lane < m) {
            r = g_csr_row[s + base + lane];
            w = g_csr_w[s + base + lane];
        }
        #pragma unroll 4
        for (int j = 0; j < m; j++) {
            int rj = __shfl_sync(0xffffffffu, r, j);
            float wj = __shfl_sync(0xffffffffu, w, j);
            float4 v = __ldg(&xwv[(size_t)rj * 32 + lane]);
            acc.x = fmaf(wj, v.x, acc.x);
            acc.y = fmaf(wj, v.y, acc.y);
            acc.z = fmaf(wj, v.z, acc.z);
            acc.w = fmaf(wj, v.w, acc.w);
        }
    }
    float4 o = make_float4(fmaxf(acc.x, 0.0f), fmaxf(acc.y, 0.0f),
                           fmaxf(acc.z, 0.0f), fmaxf(acc.w, 0.0f));
    *(float4*)&out[(size_t)warp * F + lane * 4] = o;
}

// ---------------- segment-max pool ----------------
__global__ void k_pool(const float* __restrict__ h, const void* __restrict__ batch, int n) {
    int col = threadIdx.x;
    int start = blockIdx.x * 128;
    if (start >= n) return;
    int is64 = g_idx64;
    int end = min(start + 128, n);
    int cur = load_idx(batch, start, is64);
    float m = 0.0f;
    for (int i = start; i < end; i++) {
        int g = load_idx(batch, i, is64);
        float v = h[(size_t)i * F + col];
        if (g != cur) {
            atomicMax((int*)&g_pool[cur * F + col], __float_as_int(m));
            cur = g;
            m = v;
        } else {
            m = fmaxf(m, v);
        }
    }
    atomicMax((int*)&g_pool[cur * F + col], __float_as_int(m));
}

// ---------------- head ----------------
__global__ void k_head(const float* __restrict__ Wl, const float* __restrict__ bl,
                       float* __restrict__ out) {
    int t = blockIdx.x * blockDim.x + threadIdx.x;
    if (t >= N_GRAPHS * N_CLS) return;
    int g = t / N_CLS, cls = t % N_CLS;
    float s = bl[cls];
    #pragma unroll 8
    for (int c = 0; c < F; c++)
        s = fmaf(g_pool[g * F + c], Wl[c * N_CLS + cls], s);
    out[t] = s;
}

// ---------------- launch: R8-proven fork/join, whole-kernel boundaries ----------------
extern "C" void kernel_launch(void* const* d_in, const int* in_sizes, int n_in,
                              void* d_out, int out_size) {
    const float* x     = (const float*)d_in[0];
    const void*  ei    = d_in[1];
    const float* ew    = (const float*)d_in[2];
    const void*  batch = d_in[3];
    const float* W1 = (const float*)d_in[4];
    const float* b1 = (const float*)d_in[5];
    const float* W2 = (const float*)d_in[6];
    const float* b2 = (const float*)d_in[7];
    const float* W3 = (const float*)d_in[8];
    const float* b3 = (const float*)d_in[9];
    const float* Wl = (const float*)d_in[10];
    const float* bl = (const float*)d_in[11];
    float* out = (float*)d_out;

    int n = in_sizes[0] / F;
    int E = in_sizes[2];

    float *p_xw, *p_h;
    cudaGetSymbolAddress((void**)&p_xw, g_xw);
    cudaGetSymbolAddress((void**)&p_h,  g_h);

    const int smem_bytes = 2 * 128 * PAD * (int)sizeof(float);  // 135168 B
    cudaFuncSetAttribute(k_gemm_mma, cudaFuncAttributeMaxDynamicSharedMemorySize, smem_bytes);

    cudaStream_t s1, s2;
    cudaStreamCreateWithFlags(&s1, cudaStreamNonBlocking);
    cudaStreamCreateWithFlags(&s2, cudaStreamNonBlocking);
    cudaEvent_t eFork, eG1, eFork2, eDinv;
    cudaEventCreateWithFlags(&eFork,  cudaEventDisableTiming);
    cudaEventCreateWithFlags(&eG1,    cudaEventDisableTiming);
    cudaEventCreateWithFlags(&eFork2, cudaEventDisableTiming);
    cudaEventCreateWithFlags(&eDinv,  cudaEventDisableTiming);

    int tb = 256;
    int eg = (E + tb - 1) / tb;
    int ng = (n + tb - 1) / tb;
    int gemm_grid = (n + 127) / 128;
    int gath_grid = (n * 32 + tb - 1) / tb;

    // fork GEMM1 (independent of graph precompute) onto s1
    cudaEventRecord(eFork, 0);
    cudaStreamWaitEvent(s1, eFork, 0);
    k_gemm_mma<<<gemm_grid, 256, smem_bytes, s1>>>(x, W1, p_xw, n);
    cudaEventRecord(eG1, s1);

    // CSR + normalization chain on default stream
    k_init<<<ng, tb>>>((const int*)ei, E, n);
    k_edge1<<<eg, tb>>>(ei, ew, E);
    cudaEventRecord(eFork2, 0);
    cudaStreamWaitEvent(s2, eFork2, 0);
    k_dinv<<<ng, tb, 0, s2>>>(n);
    cudaEventRecord(eDinv, s2);
    k_scan<<<1, 1024>>>(n);
    cudaStreamWaitEvent(0, eDinv, 0);
    k_fill<<<eg, tb>>>(ei, ew, E);
    cudaStreamWaitEvent(0, eG1, 0);   // join GEMM1

    // layer 1
    k_gather<<<gath_grid, tb>>>(p_xw, b1, p_h, n);
    // layer 2
    k_gemm_mma<<<gemm_grid, 256, smem_bytes>>>(p_h, W2, p_xw, n);
    k_gather<<<gath_grid, tb>>>(p_xw, b2, p_h, n);
    // layer 3
    k_gemm_mma<<<gemm_grid, 256, smem_bytes>>>(p_h, W3, p_xw, n);
    k_gather<<<gath_grid, tb>>>(p_xw, b3, p_h, n);

    // pool + head
    k_pool<<<(n + 127) / 128, 128>>>(p_h, batch, n);
    k_head<<<(N_GRAPHS * N_CLS + 127) / 128, 128>>>(Wl, bl, out);

    cudaEventDestroy(eFork);
    cudaEventDestroy(eG1);
    cudaEventDestroy(eFork2);
    cudaEventDestroy(eDinv);
    cudaStreamDestroy(s1);
    cudaStreamDestroy(s2);
}

// round 13
// speedup vs baseline: 2.4276x; 1.1879x over previous
#include <cuda_runtime.h>
#include <cuda_bf16.h>
#include <math.h>
#include <stdint.h>

#define N_MAX 50000
#define E_MAX 800000
#define F 128
#define N_GRAPHS 64
#define N_CLS 10
#define PAD 132   // floats per SMEM row (128 + 4 to break bank conflicts)

// ---------------- device scratch ----------------
__device__ float g_xw[(size_t)N_MAX * F];      // h @ W
__device__ float g_h[(size_t)N_MAX * F];       // layer output (relu'd)
__device__ float g_deg[N_MAX];                 // raw sum of ew at target
__device__ float g_dinv[N_MAX];
__device__ float g_dinv2[N_MAX];
__device__ float g_sumsq;
__device__ float g_pool[N_GRAPHS * F];
__device__ int   g_idx64;
__device__ int   g_total;                      // CSR slot allocator
// CSR by target node (built once, reused 3 layers)
__device__ int   g_cnt[N_MAX];
__device__ int   g_start[N_MAX];
__device__ int   g_cursor[N_MAX];
__device__ int   g_csr_row[E_MAX];
__device__ float g_csr_w[E_MAX];

// ---------------- index helpers ----------------
__device__ __forceinline__ int load_idx(const void* p, long long i, int is64) {
    if (is64) return (int)((const long long*)p)[i];
    return ((const int*)p)[i];
}

// ---------------- init: dtype detect (block 0) + resets ----------------
__global__ void k_init(const int* __restrict__ ei32, int E, int n) {
    int i = blockIdx.x * blockDim.x + threadIdx.x;
    if (i < n) { g_deg[i] = 0.0f; g_cnt[i] = 0; g_cursor[i] = 0; }
    if (i < N_GRAPHS * F) ((int*)g_pool)[i] = 0;
    if (i == 0) { g_sumsq = 0.0f; g_total = 0; }
    if (blockIdx.x == 0) {
        __shared__ int anynz;
        if (threadIdx.x == 0) anynz = 0;
        __syncthreads();
        int samples = min(E, 2048);
        for (int t = threadIdx.x; t < samples; t += blockDim.x)
            if (ei32[2 * t + 1] != 0) anynz = 1;
        __syncthreads();
        if (threadIdx.x == 0) g_idx64 = anynz ? 0 : 1;
    }
}

// one edge pass: sumsq reduction + raw deg accumulation + cnt
__global__ void k_edge1(const void* __restrict__ ei, const float* __restrict__ ew, int E) {
    int e = blockIdx.x * blockDim.x + threadIdx.x;
    int is64 = g_idx64;
    float v = 0.0f;
    if (e < E) {
        v = ew[e];
        int c = load_idx(ei, (long long)E + e, is64);
        atomicAdd(&g_deg[c], v);
        atomicAdd(&g_cnt[c], 1);
    }
    float s = v * v;
    #pragma unroll
    for (int o = 16; o > 0; o >>= 1) s += __shfl_down_sync(0xffffffffu, s, o);
    __shared__ float ws[8];
    int lane = threadIdx.x & 31, wid = threadIdx.x >> 5;
    if (lane == 0) ws[wid] = s;
    __syncthreads();
    if (wid == 0) {
        s = (lane < (blockDim.x >> 5)) ? ws[lane] : 0.0f;
        #pragma unroll
        for (int o = 4; o > 0; o >>= 1) s += __shfl_down_sync(0xffffffffu, s, o);
        if (lane == 0) atomicAdd(&g_sumsq, s);
    }
}

__device__ __forceinline__ float inv_l2norm() {
    return 1.0f / fmaxf(sqrtf(g_sumsq), 1e-12f);
}

// dinv + CSR slot allocation (order-free: replaces the prefix scan)
__global__ void k_dinv_alloc(int n) {
    int i = blockIdx.x * blockDim.x + threadIdx.x;
    if (i >= n) return;
    float d = 1.0f + inv_l2norm() * g_deg[i];
    float di = (d > 0.0f) ? rsqrtf(d) : 0.0f;
    g_dinv[i] = di;
    g_dinv2[i] = di * di;
    int c = g_cnt[i];
    g_start[i] = c ? atomicAdd(&g_total, c) : 0;
}

__global__ void k_fill(const void* __restrict__ ei, const float* __restrict__ ew, int E) {
    int e = blockIdx.x * blockDim.x + threadIdx.x;
    if (e >= E) return;
    int is64 = g_idx64;
    float invn = inv_l2norm();
    int r = load_idx(ei, e, is64);
    int c = load_idx(ei, (long long)E + e, is64);
    float w = g_dinv[r] * (ew[e] * invn) * g_dinv[c];
    int p = atomicAdd(&g_cursor[c], 1);
    int slot = g_start[c] + p;
    g_csr_row[slot] = r;
    g_csr_w[slot] = w;
}

// ---------------- tf32 mma.sync GEMM: xw = A @ W ----------------
__device__ __forceinline__ uint32_t f2tf32(float f) {
    uint32_t r;
    asm("cvt.rna.tf32.f32 %0, %1;" : "=r"(r) : "f"(f));
    return r;
}

__global__ void __launch_bounds__(256, 1) k_gemm_mma(const float* __restrict__ A,
                                                     const float* __restrict__ W,
                                                     float* __restrict__ xw, int n) {
    extern __shared__ uint32_t sm[];
    uint32_t* As = sm;               // 128 x PAD
    uint32_t* Ws = sm + 128 * PAD;   // 128 x PAD
    int tid = threadIdx.x;
    int row0 = blockIdx.x * 128;

    const float4* w4 = (const float4*)W;
    #pragma unroll
    for (int j = 0; j < 16; j++) {
        int idx4 = tid + j * 256;
        int el = idx4 * 4;
        int r = el >> 7, c = el & 127;
        float4 v = w4[idx4];
        uint32_t* dst = &Ws[r * PAD + c];
        dst[0] = f2tf32(v.x); dst[1] = f2tf32(v.y);
        dst[2] = f2tf32(v.z); dst[3] = f2tf32(v.w);
    }
    const float4* a4 = (const float4*)A;
    #pragma unroll
    for (int j = 0; j < 16; j++) {
        int idx4 = tid + j * 256;
        int el = idx4 * 4;
        int r = el >> 7, c = el & 127;
        int gr = row0 + r;
        float4 v = (gr < n) ? a4[(size_t)gr * 32 + (c >> 2)] : make_float4(0.f, 0.f, 0.f, 0.f);
        uint32_t* dst = &As[r * PAD + c];
        dst[0] = f2tf32(v.x); dst[1] = f2tf32(v.y);
        dst[2] = f2tf32(v.z); dst[3] = f2tf32(v.w);
    }
    __syncthreads();

    int lane = tid & 31, warp = tid >> 5;
    int wm = warp >> 1, wn = warp & 1;
    int m0 = wm * 32, n0 = wn * 64;
    int grp = lane >> 2, thr = lane & 3;

    float acc[2][8][4];
    #pragma unroll
    for (int f = 0; f < 2; f++)
        #pragma unroll
        for (int g = 0; g < 8; g++)
            #pragma unroll
            for (int q = 0; q < 4; q++) acc[f][g][q] = 0.0f;

    #pragma unroll 4
    for (int s = 0; s < 16; s++) {
        int k0 = s * 8;
        uint32_t a[2][4];
        #pragma unroll
        for (int f = 0; f < 2; f++) {
            int rl = m0 + f * 16 + grp;
            a[f][0] = As[rl * PAD + k0 + thr];
            a[f][1] = As[(rl + 8) * PAD + k0 + thr];
            a[f][2] = As[rl * PAD + k0 + 4 + thr];
            a[f][3] = As[(rl + 8) * PAD + k0 + 4 + thr];
        }
        #pragma unroll
        for (int g = 0; g < 8; g++) {
            uint32_t b0 = Ws[(k0 + thr) * PAD + n0 + g * 8 + grp];
            uint32_t b1 = Ws[(k0 + 4 + thr) * PAD + n0 + g * 8 + grp];
            #pragma unroll
            for (int f = 0; f < 2; f++) {
                asm volatile(
                    "mma.sync.aligned.m16n8k8.row.col.f32.tf32.tf32.f32 "
                    "{%0,%1,%2,%3}, {%4,%5,%6,%7}, {%8,%9}, {%0,%1,%2,%3};"
                    : "+f"(acc[f][g][0]), "+f"(acc[f][g][1]),
                      "+f"(acc[f][g][2]), "+f"(acc[f][g][3])
                    : "r"(a[f][0]), "r"(a[f][1]), "r"(a[f][2]), "r"(a[f][3]),
                      "r"(b0), "r"(b1));
            }
        }
    }

    #pragma unroll
    for (int f = 0; f < 2; f++) {
        int rl = row0 + m0 + f * 16 + grp;
        int rh = rl + 8;
        #pragma unroll
        for (int g = 0; g < 8; g++) {
            int col = n0 + g * 8 + thr * 2;
            if (rl < n)
                *(float2*)&xw[(size_t)rl * F + col] = make_float2(acc[f][g][0], acc[f][g][1]);
            if (rh < n)
                *(float2*)&xw[(size_t)rh * F + col] = make_float2(acc[f][g][2], acc[f][g][3]);
        }
    }
}

// ---------------- CSR gather: out = relu(b + dinv2*xw[i] + sum w*xw[r]) ----------------
__global__ void k_gather(const float* __restrict__ xw, const float* __restrict__ b,
                         float* __restrict__ out, int n) {
    int warp = (blockIdx.x * blockDim.x + threadIdx.x) >> 5;
    int lane = threadIdx.x & 31;
    if (warp >= n) return;

    const float4* xwv = (const float4*)xw;
    float4 bb = *(const float4*)&b[lane * 4];
    float d2 = g_dinv2[warp];
    float4 xv = __ldg(&xwv[(size_t)warp * 32 + lane]);
    float4 acc = make_float4(fmaf(d2, xv.x, bb.x), fmaf(d2, xv.y, bb.y),
                             fmaf(d2, xv.z, bb.z), fmaf(d2, xv.w, bb.w));

    int s = g_start[warp];
    int cnt = g_cnt[warp];
    for (int base = 0; base < cnt; base += 32) {
        int m = min(32, cnt - base);
        int r = 0; float w = 0.0f;
        if (lane < m) {
            r = g_csr_row[s + base + lane];
            w = g_csr_w[s + base + lane];
        }
        #pragma unroll 4
        for (int j = 0; j < m; j++) {
            int rj = __shfl_sync(0xffffffffu, r, j);
            float wj = __shfl_sync(0xffffffffu, w, j);
            float4 v = __ldg(&xwv[(size_t)rj * 32 + lane]);
            acc.x = fmaf(wj, v.x, acc.x);
            acc.y = fmaf(wj, v.y, acc.y);
            acc.z = fmaf(wj, v.z, acc.z);
            acc.w = fmaf(wj, v.w, acc.w);
        }
    }
    float4 o = make_float4(fmaxf(acc.x, 0.0f), fmaxf(acc.y, 0.0f),
                           fmaxf(acc.z, 0.0f), fmaxf(acc.w, 0.0f));
    *(float4*)&out[(size_t)warp * F + lane * 4] = o;
}

// ---------------- segment-max pool ----------------
__global__ void k_pool(const float* __restrict__ h, const void* __restrict__ batch, int n) {
    int col = threadIdx.x;
    int start = blockIdx.x * 128;
    if (start >= n) return;
    int is64 = g_idx64;
    int end = min(start + 128, n);
    int cur = load_idx(batch, start, is64);
    float m = 0.0f;
    for (int i = start; i < end; i++) {
        int g = load_idx(batch, i, is64);
        float v = h[(size_t)i * F + col];
        if (g != cur) {
            atomicMax((int*)&g_pool[cur * F + col], __float_as_int(m));
            cur = g;
            m = v;
        } else {
            m = fmaxf(m, v);
        }
    }
    atomicMax((int*)&g_pool[cur * F + col], __float_as_int(m));
}

// ---------------- head ----------------
__global__ void k_head(const float* __restrict__ Wl, const float* __restrict__ bl,
                       float* __restrict__ out) {
    int t = blockIdx.x * blockDim.x + threadIdx.x;
    if (t >= N_GRAPHS * N_CLS) return;
    int g = t / N_CLS, cls = t % N_CLS;
    float s = bl[cls];
    #pragma unroll 8
    for (int c = 0; c < F; c++)
        s = fmaf(g_pool[g * F + c], Wl[c * N_CLS + cls], s);
    out[t] = s;
}

// ---------------- launch: GEMM1 fork + scan-free CSR chain ----------------
extern "C" void kernel_launch(void* const* d_in, const int* in_sizes, int n_in,
                              void* d_out, int out_size) {
    const float* x     = (const float*)d_in[0];
    const void*  ei    = d_in[1];
    const float* ew    = (const float*)d_in[2];
    const void*  batch = d_in[3];
    const float* W1 = (const float*)d_in[4];
    const float* b1 = (const float*)d_in[5];
    const float* W2 = (const float*)d_in[6];
    const float* b2 = (const float*)d_in[7];
    const float* W3 = (const float*)d_in[8];
    const float* b3 = (const float*)d_in[9];
    const float* Wl = (const float*)d_in[10];
    const float* bl = (const float*)d_in[11];
    float* out = (float*)d_out;

    int n = in_sizes[0] / F;
    int E = in_sizes[2];

    float *p_xw, *p_h;
    cudaGetSymbolAddress((void**)&p_xw, g_xw);
    cudaGetSymbolAddress((void**)&p_h,  g_h);

    const int smem_bytes = 2 * 128 * PAD * (int)sizeof(float);  // 135168 B
    cudaFuncSetAttribute(k_gemm_mma, cudaFuncAttributeMaxDynamicSharedMemorySize, smem_bytes);

    cudaStream_t s1;
    cudaStreamCreateWithFlags(&s1, cudaStreamNonBlocking);
    cudaEvent_t eFork, eG1;
    cudaEventCreateWithFlags(&eFork, cudaEventDisableTiming);
    cudaEventCreateWithFlags(&eG1,   cudaEventDisableTiming);

    int tb = 256;
    int eg = (E + tb - 1) / tb;
    int ng = (n + tb - 1) / tb;
    int gemm_grid = (n + 127) / 128;
    int gath_grid = (n * 32 + tb - 1) / tb;

    // fork GEMM1 (independent of graph precompute) onto s1
    cudaEventRecord(eFork, 0);
    cudaStreamWaitEvent(s1, eFork, 0);
    k_gemm_mma<<<gemm_grid, 256, smem_bytes, s1>>>(x, W1, p_xw, n);
    cudaEventRecord(eG1, s1);

    // scan-free CSR + normalization chain on default stream
    k_init<<<ng, tb>>>((const int*)ei, E, n);
    k_edge1<<<eg, tb>>>(ei, ew, E);
    k_dinv_alloc<<<ng, tb>>>(n);
    k_fill<<<eg, tb>>>(ei, ew, E);
    cudaStreamWaitEvent(0, eG1, 0);   // join GEMM1

    // layer 1
    k_gather<<<gath_grid, tb>>>(p_xw, b1, p_h, n);
    // layer 2
    k_gemm_mma<<<gemm_grid, 256, smem_bytes>>>(p_h, W2, p_xw, n);
    k_gather<<<gath_grid, tb>>>(p_xw, b2, p_h, n);
    // layer 3
    k_gemm_mma<<<gemm_grid, 256, smem_bytes>>>(p_h, W3, p_xw, n);
    k_gather<<<gath_grid, tb>>>(p_xw, b3, p_h, n);

    // pool + head
    k_pool<<<(n + 127) / 128, 128>>>(p_h, batch, n);
    k_head<<<(N_GRAPHS * N_CLS + 127) / 128, 128>>>(Wl, bl, out);

    cudaEventDestroy(eFork);
    cudaEventDestroy(eG1);
    cudaStreamDestroy(s1);
}